// round 2
// baseline (speedup 1.0000x reference)
#include <cuda_runtime.h>
#include <cuda_bf16.h>
#include <math.h>

// Problem dims (fixed for this bench)
#define BB 64
#define LL 2048
#define DD 1024
#define VV 50257
#define TOPK 5

#define LCHUNK 8           // L split into 8 chunks of 256
#define TN 64              // GEMM N tile (lexicon rows per block)
#define TK 32              // GEMM K tile
#define BSPAD 68           // padded Bs row stride (16B aligned, conflict-free reads)

// Scratch (device globals; no allocations allowed)
__device__ float g_part[LCHUNK][BB][DD];   // mean-pool partials (2 MB)
__device__ float g_tsT[DD][BB];            // transposed pooled embeddings (k-major)
__device__ float g_xnorm[BB];
__device__ float g_ynorm[VV];

// ---------------------------------------------------------------------------
// Kernel 1: mean-pool partial sums. grid=(LCHUNK, BB), block=1024 (one d each)
// ---------------------------------------------------------------------------
__global__ void __launch_bounds__(1024) mean_partial_kernel(const float* __restrict__ patch) {
    int d = threadIdx.x;
    int c = blockIdx.x;
    int b = blockIdx.y;
    const float* p = patch + ((size_t)b * LL + (size_t)c * (LL / LCHUNK)) * DD + d;
    float s = 0.f;
    #pragma unroll 8
    for (int l = 0; l < LL / LCHUNK; l++) {
        s += p[(size_t)l * DD];
    }
    g_part[c][b][d] = s;
}

// ---------------------------------------------------------------------------
// Kernel 2: finalize mean, write transposed ts, compute x norms.
// grid=BB, block=1024
// ---------------------------------------------------------------------------
__global__ void __launch_bounds__(1024) finalize_kernel() {
    int b = blockIdx.x;
    int d = threadIdx.x;
    float s = 0.f;
    #pragma unroll
    for (int c = 0; c < LCHUNK; c++) s += g_part[c][b][d];
    float ts = s * (1.0f / (float)LL);
    g_tsT[d][b] = ts;

    // block reduce ts*ts -> xnorm
    float val = ts * ts;
    #pragma unroll
    for (int o = 16; o; o >>= 1) val += __shfl_xor_sync(0xFFFFFFFFu, val, o);
    __shared__ float red[32];
    if ((d & 31) == 0) red[d >> 5] = val;
    __syncthreads();
    if (d < 32) {
        float v2 = red[d];
        #pragma unroll
        for (int o = 16; o; o >>= 1) v2 += __shfl_xor_sync(0xFFFFFFFFu, v2, o);
        if (d == 0) g_xnorm[b] = sqrtf(v2);
    }
}

// ---------------------------------------------------------------------------
// Kernel 3: lexicon row norms. grid=VV, block=256 (float4 per thread)
// ---------------------------------------------------------------------------
__global__ void __launch_bounds__(256) ynorm_kernel(const float* __restrict__ lex) {
    int v = blockIdx.x;
    int t = threadIdx.x;
    const float4* row = reinterpret_cast<const float4*>(lex + (size_t)v * DD);
    float4 f = row[t];
    float s = f.x * f.x + f.y * f.y + f.z * f.z + f.w * f.w;
    #pragma unroll
    for (int o = 16; o; o >>= 1) s += __shfl_xor_sync(0xFFFFFFFFu, s, o);
    __shared__ float red[8];
    if ((t & 31) == 0) red[t >> 5] = s;
    __syncthreads();
    if (t == 0) {
        float tot = 0.f;
        #pragma unroll
        for (int w = 0; w < 8; w++) tot += red[w];
        g_ynorm[v] = sqrtf(tot);
    }
}

// ---------------------------------------------------------------------------
// Kernel 4: similarity GEMM. dots[b][v] = ts[b,:] . lex[v,:], normalized.
// grid = ceil(VV/TN), block = 256. 64x64 output tile, 4x4 microtile.
// ---------------------------------------------------------------------------
__global__ void __launch_bounds__(256) gemm_kernel(const float* __restrict__ lex,
                                                   float* __restrict__ out_sim) {
    __shared__ float As[TK][BB];        // k-major ts tile (contiguous copy from g_tsT)
    __shared__ float Bs[TK][BSPAD];     // k-major lexicon tile (transposed on store)
    __shared__ float s_xn[BB];
    __shared__ float s_yn[TN];

    int tid = threadIdx.x;
    int v0 = blockIdx.x * TN;
    int tx = tid & 15;       // n direction
    int ty = tid >> 4;       // m direction

    if (tid < BB) s_xn[tid] = g_xnorm[tid];
    if (tid < TN) {
        int v = v0 + tid;
        s_yn[tid] = (v < VV) ? g_ynorm[v] : 1.f;
    }

    float acc[4][4];
    #pragma unroll
    for (int i = 0; i < 4; i++)
        #pragma unroll
        for (int j = 0; j < 4; j++) acc[i][j] = 0.f;

    for (int k0 = 0; k0 < DD; k0 += TK) {
        __syncthreads();
        // Load A tile: 2048 contiguous floats from g_tsT[k0..k0+31][*]
        {
            const float4* src = reinterpret_cast<const float4*>(&g_tsT[k0][0]);
            float4* dst = reinterpret_cast<float4*>(&As[0][0]);
            dst[tid]       = src[tid];
            dst[tid + 256] = src[tid + 256];
        }
        // Load B tile: 64 rows x 32 k, transpose into Bs[k][n]
        #pragma unroll
        for (int i = 0; i < 2; i++) {
            int idx4 = tid + i * 256;          // 0..511
            int n = idx4 >> 3;                 // 0..63
            int kq = (idx4 & 7) << 2;          // 0,4,...,28
            int v = v0 + n;
            float4 val = make_float4(0.f, 0.f, 0.f, 0.f);
            if (v < VV)
                val = *reinterpret_cast<const float4*>(&lex[(size_t)v * DD + k0 + kq]);
            Bs[kq + 0][n] = val.x;
            Bs[kq + 1][n] = val.y;
            Bs[kq + 2][n] = val.z;
            Bs[kq + 3][n] = val.w;
        }
        __syncthreads();
        #pragma unroll
        for (int k = 0; k < TK; k++) {
            float4 a = *reinterpret_cast<float4*>(&As[k][ty << 2]);
            float4 bv = *reinterpret_cast<float4*>(&Bs[k][tx << 2]);
            float av[4] = {a.x, a.y, a.z, a.w};
            float bw[4] = {bv.x, bv.y, bv.z, bv.w};
            #pragma unroll
            for (int i = 0; i < 4; i++)
                #pragma unroll
                for (int j = 0; j < 4; j++)
                    acc[i][j] = fmaf(av[i], bw[j], acc[i][j]);
        }
    }

    // Epilogue: normalize and store (scalar stores: V is odd, no vec alignment)
    #pragma unroll
    for (int i = 0; i < 4; i++) {
        int m = (ty << 2) + i;
        float xn = s_xn[m];
        #pragma unroll
        for (int j = 0; j < 4; j++) {
            int n = (tx << 2) + j;
            int v = v0 + n;
            if (v < VV) {
                float den = fmaxf(xn * s_yn[n], 1e-8f);
                out_sim[(size_t)m * VV + v] = acc[i][j] / den;
            }
        }
    }
}

// ---------------------------------------------------------------------------
// Kernel 5: top-k (5 masked argmax passes) + gather. grid=BB, block=1024
// Tie-break: lowest index wins (matches jax.lax.top_k).
// ---------------------------------------------------------------------------
__global__ void __launch_bounds__(1024) topk_kernel(const float* __restrict__ lex,
                                                    const float* __restrict__ sim,
                                                    float* __restrict__ out_topk) {
    int b = blockIdx.x;
    int t = threadIdx.x;
    __shared__ float s_val[32];
    __shared__ int   s_idx[32];
    __shared__ int   sel[TOPK];

    const float* row = sim + (size_t)b * VV;

    for (int j = 0; j < TOPK; j++) {
        float bv = -1e30f;
        int bi = 0x7FFFFFFF;
        for (int v = t; v < VV; v += 1024) {
            bool skip = false;
            #pragma unroll
            for (int jj = 0; jj < TOPK; jj++)
                if (jj < j && sel[jj] == v) skip = true;
            float x = skip ? -1e30f : row[v];
            if (x > bv || (x == bv && v < bi)) { bv = x; bi = v; }
        }
        #pragma unroll
        for (int o = 16; o; o >>= 1) {
            float ov = __shfl_xor_sync(0xFFFFFFFFu, bv, o);
            int   oi = __shfl_xor_sync(0xFFFFFFFFu, bi, o);
            if (ov > bv || (ov == bv && oi < bi)) { bv = ov; bi = oi; }
        }
        if ((t & 31) == 0) { s_val[t >> 5] = bv; s_idx[t >> 5] = bi; }
        __syncthreads();
        if (t == 0) {
            for (int w = 1; w < 32; w++) {
                if (s_val[w] > bv || (s_val[w] == bv && s_idx[w] < bi)) {
                    bv = s_val[w]; bi = s_idx[w];
                }
            }
            sel[j] = bi;
        }
        __syncthreads();
    }

    // Gather top-k lexicon rows
    for (int j = 0; j < TOPK; j++) {
        const float* src = lex + (size_t)sel[j] * DD;
        float* dst = out_topk + ((size_t)b * TOPK + j) * DD;
        for (int d = t; d < DD; d += 1024) dst[d] = src[d];
    }
}

// ---------------------------------------------------------------------------
extern "C" void kernel_launch(void* const* d_in, const int* in_sizes, int n_in,
                              void* d_out, int out_size) {
    const float* patch = (const float*)d_in[0];
    const float* lex   = (const float*)d_in[1];
    float* out      = (float*)d_out;
    float* out_topk = out;                                  // [64][5][1024]
    float* out_sim  = out + (size_t)BB * TOPK * DD;         // [64][50257]

    mean_partial_kernel<<<dim3(LCHUNK, BB), 1024>>>(patch);
    finalize_kernel<<<BB, 1024>>>();
    ynorm_kernel<<<VV, 256>>>(lex);
    gemm_kernel<<<(VV + TN - 1) / TN, 256>>>(lex, out_sim);
    topk_kernel<<<BB, 1024>>>(lex, out_sim, out_topk);
}

// round 3
// speedup vs baseline: 1.5657x; 1.5657x over previous
#include <cuda_runtime.h>
#include <cuda_bf16.h>
#include <math.h>
#include <cstdint>

// Problem dims (fixed for this bench)
#define BB 64
#define LL 2048
#define DD 1024
#define VV 50257
#define TOPK 5

#define NCHUNK 16
#define LPC (LL / NCHUNK)        // 128 rows per chunk

#define TNB 128                  // GEMM N tile
#define TK 32                    // GEMM K tile
#define KPAD 36                  // padded k stride (conflict-free: 36 mod 32 = 4)
#define NCAND 256

// Scratch (device globals; no allocations allowed)
__device__ float4 g_part[NCHUNK][BB][DD / 4];  // mean-pool partials (4 MB)
__device__ float  g_tse[BB][DD];               // exact fp32 pooled embeddings
__device__ float  g_ts32[BB][DD];              // tf32-rounded pooled embeddings
__device__ float  g_xnorm[BB];
__device__ float  g_ynorm[VV];

__device__ __forceinline__ float tf32r(float x) {
    uint32_t o;
    asm("cvt.rna.tf32.f32 %0, %1;" : "=r"(o) : "f"(x));
    return __uint_as_float(o);
}

__device__ __forceinline__ void mma_tf32(float c[4],
                                         uint32_t a0, uint32_t a1, uint32_t a2, uint32_t a3,
                                         uint32_t b0, uint32_t b1) {
    asm volatile(
        "mma.sync.aligned.m16n8k8.row.col.f32.tf32.tf32.f32 "
        "{%0,%1,%2,%3}, {%4,%5,%6,%7}, {%8,%9}, {%0,%1,%2,%3};"
        : "+f"(c[0]), "+f"(c[1]), "+f"(c[2]), "+f"(c[3])
        : "r"(a0), "r"(a1), "r"(a2), "r"(a3), "r"(b0), "r"(b1));
}

// ---------------------------------------------------------------------------
// Kernel 1: mean-pool partial sums. grid=(NCHUNK, BB), block=256 (float4 each)
// ---------------------------------------------------------------------------
__global__ void __launch_bounds__(256) mean_partial_kernel(const float* __restrict__ patch) {
    int t = threadIdx.x;
    int c = blockIdx.x;
    int b = blockIdx.y;
    const float4* p = reinterpret_cast<const float4*>(
                          patch + ((size_t)b * LL + (size_t)c * LPC) * DD) + t;
    float4 s = make_float4(0.f, 0.f, 0.f, 0.f);
    #pragma unroll 8
    for (int l = 0; l < LPC; l++) {
        float4 v = p[(size_t)l * (DD / 4)];
        s.x += v.x; s.y += v.y; s.z += v.z; s.w += v.w;
    }
    g_part[c][b][t] = s;
}

// ---------------------------------------------------------------------------
// Kernel 2: finalize mean, write exact + tf32 ts (m-major), x norms.
// grid=BB, block=256
// ---------------------------------------------------------------------------
__global__ void __launch_bounds__(256) finalize_kernel() {
    int b = blockIdx.x;
    int t = threadIdx.x;
    float4 s = make_float4(0.f, 0.f, 0.f, 0.f);
    #pragma unroll
    for (int c = 0; c < NCHUNK; c++) {
        float4 v = g_part[c][b][t];
        s.x += v.x; s.y += v.y; s.z += v.z; s.w += v.w;
    }
    const float inv = 1.0f / (float)LL;
    s.x *= inv; s.y *= inv; s.z *= inv; s.w *= inv;
    reinterpret_cast<float4*>(g_tse[b])[t] = s;
    float4 r;
    r.x = tf32r(s.x); r.y = tf32r(s.y); r.z = tf32r(s.z); r.w = tf32r(s.w);
    reinterpret_cast<float4*>(g_ts32[b])[t] = r;

    float ss = s.x * s.x + s.y * s.y + s.z * s.z + s.w * s.w;
    #pragma unroll
    for (int o = 16; o; o >>= 1) ss += __shfl_xor_sync(0xFFFFFFFFu, ss, o);
    __shared__ float red[8];
    if ((t & 31) == 0) red[t >> 5] = ss;
    __syncthreads();
    if (t == 0) {
        float tot = 0.f;
        #pragma unroll
        for (int w = 0; w < 8; w++) tot += red[w];
        g_xnorm[b] = sqrtf(tot);
    }
}

// ---------------------------------------------------------------------------
// Kernel 3: TF32 tensor-core similarity GEMM + fused lexicon row norms.
// grid = ceil(VV/128), block = 256 (8 warps = 2 m-warps x 4 n-warps).
// Warp tile 32x32 via m16n8k8: 2 m-tiles x 4 n-tiles.
// Smem layouts [row][k] with KPAD=36: all fragment LDS are conflict-free
// (bank = 4*(lane>>2) + (lane&3) + const = lane + const).
// ---------------------------------------------------------------------------
__global__ void __launch_bounds__(256) gemm_kernel(const float* __restrict__ lex,
                                                   float* __restrict__ out_sim) {
    __shared__ float As[BB * KPAD];       // 9.2 KB
    __shared__ float Bs[TNB * KPAD];      // 18.4 KB
    __shared__ float s_xn[BB];
    __shared__ float s_yn[TNB];

    int tid = threadIdx.x;
    int v0 = blockIdx.x * TNB;
    int lane = tid & 31, wid = tid >> 5;
    int g = lane >> 2, t4 = lane & 3;
    int m_base = (wid >> 2) * 32;
    int n_base = (wid & 3) * 32;

    if (tid < BB) s_xn[tid] = g_xnorm[tid];

    float acc[2][4][4];
    #pragma unroll
    for (int mt = 0; mt < 2; mt++)
        #pragma unroll
        for (int nt = 0; nt < 4; nt++)
            #pragma unroll
            for (int r = 0; r < 4; r++) acc[mt][nt][r] = 0.f;
    float yacc[4] = {0.f, 0.f, 0.f, 0.f};

    for (int k0 = 0; k0 < DD; k0 += TK) {
        __syncthreads();
        // A tile: 64 rows x 32 k (pre-converted tf32), float4 stores
        #pragma unroll
        for (int i = 0; i < 2; i++) {
            int idx = tid + i * 256;
            int m = idx >> 3, kq = (idx & 7) << 2;
            float4 v = *reinterpret_cast<const float4*>(&g_ts32[m][k0 + kq]);
            *reinterpret_cast<float4*>(&As[m * KPAD + kq]) = v;
        }
        // B tile: 128 rows x 32 k, accumulate sumsq (fp32), convert to tf32
        #pragma unroll
        for (int i = 0; i < 4; i++) {
            int idx = tid + i * 256;
            int n = idx >> 3, kq = (idx & 7) << 2;
            int v = v0 + n;
            float4 w = make_float4(0.f, 0.f, 0.f, 0.f);
            if (v < VV)
                w = *reinterpret_cast<const float4*>(&lex[(size_t)v * DD + k0 + kq]);
            yacc[i] += w.x * w.x + w.y * w.y + w.z * w.z + w.w * w.w;
            float4 r;
            r.x = tf32r(w.x); r.y = tf32r(w.y); r.z = tf32r(w.z); r.w = tf32r(w.w);
            *reinterpret_cast<float4*>(&Bs[n * KPAD + kq]) = r;
        }
        __syncthreads();
        #pragma unroll
        for (int ks = 0; ks < 4; ks++) {
            int kk = ks * 8 + t4;
            uint32_t a[2][4], bf[4][2];
            #pragma unroll
            for (int mt = 0; mt < 2; mt++) {
                int r0 = m_base + 16 * mt + g;
                a[mt][0] = __float_as_uint(As[r0 * KPAD + kk]);
                a[mt][1] = __float_as_uint(As[(r0 + 8) * KPAD + kk]);
                a[mt][2] = __float_as_uint(As[r0 * KPAD + kk + 4]);
                a[mt][3] = __float_as_uint(As[(r0 + 8) * KPAD + kk + 4]);
            }
            #pragma unroll
            for (int nt = 0; nt < 4; nt++) {
                int c0 = n_base + 8 * nt + g;
                bf[nt][0] = __float_as_uint(Bs[c0 * KPAD + kk]);
                bf[nt][1] = __float_as_uint(Bs[c0 * KPAD + kk + 4]);
            }
            #pragma unroll
            for (int mt = 0; mt < 2; mt++)
                #pragma unroll
                for (int nt = 0; nt < 4; nt++)
                    mma_tf32(acc[mt][nt], a[mt][0], a[mt][1], a[mt][2], a[mt][3],
                             bf[nt][0], bf[nt][1]);
        }
    }

    // Fused y norms: reduce the 8 k-slice partials per row (groups of 8 lanes)
    #pragma unroll
    for (int i = 0; i < 4; i++) {
        float ys = yacc[i];
        ys += __shfl_down_sync(0xFFFFFFFFu, ys, 4, 8);
        ys += __shfl_down_sync(0xFFFFFFFFu, ys, 2, 8);
        ys += __shfl_down_sync(0xFFFFFFFFu, ys, 1, 8);
        if ((tid & 7) == 0) {
            int n = (tid + i * 256) >> 3;
            float yn = sqrtf(ys);
            s_yn[n] = yn;
            if (v0 + n < VV) g_ynorm[v0 + n] = yn;
        }
    }
    __syncthreads();

    // Epilogue: normalize, store. c0:(g,2t4) c1:(g,2t4+1) c2:(g+8,2t4) c3:(g+8,2t4+1)
    #pragma unroll
    for (int mt = 0; mt < 2; mt++) {
        int m0 = m_base + 16 * mt + g;
        float xn0 = s_xn[m0], xn1 = s_xn[m0 + 8];
        #pragma unroll
        for (int nt = 0; nt < 4; nt++) {
            int ncol = n_base + 8 * nt + 2 * t4;
            #pragma unroll
            for (int j = 0; j < 2; j++) {
                int v = v0 + ncol + j;
                if (v < VV) {
                    float yn = s_yn[ncol + j];
                    out_sim[(size_t)m0 * VV + v] =
                        acc[mt][nt][j] / fmaxf(xn0 * yn, 1e-8f);
                    out_sim[(size_t)(m0 + 8) * VV + v] =
                        acc[mt][nt][2 + j] / fmaxf(xn1 * yn, 1e-8f);
                }
            }
        }
    }
}

// ---------------------------------------------------------------------------
// Kernel 4: exact top-k. Approx top-5 on tf32 sims -> candidate set within
// 5e-4 of the 5th value -> exact fp32 recompute -> exact (val desc, idx asc)
// selection -> gather. grid=BB, block=1024.
// ---------------------------------------------------------------------------
__global__ void __launch_bounds__(1024) topk_kernel(const float* __restrict__ lex,
                                                    const float* __restrict__ sim,
                                                    float* __restrict__ out_topk) {
    int b = blockIdx.x;
    int t = threadIdx.x;
    __shared__ float s_val[32];
    __shared__ int   s_idx[32];
    __shared__ int   selv[TOPK];      // approx top-5 lexicon indices
    __shared__ float s_thresh;
    __shared__ int   cand[NCAND];
    __shared__ float cval[NCAND];
    __shared__ int   ncand;
    __shared__ int   selci[TOPK];     // final: candidate-slot index
    __shared__ int   selfin[TOPK];    // final: lexicon index (sorted desc)

    const float* row = sim + (size_t)b * VV;

    // Phase 1: approx top-5 (masked argmax passes)
    for (int j = 0; j < TOPK; j++) {
        float bv = -1e30f;
        int bi = 0x7FFFFFFF;
        for (int v = t; v < VV; v += 1024) {
            bool skip = false;
            #pragma unroll
            for (int jj = 0; jj < TOPK; jj++)
                if (jj < j && selv[jj] == v) skip = true;
            float x = skip ? -1e30f : row[v];
            if (x > bv || (x == bv && v < bi)) { bv = x; bi = v; }
        }
        #pragma unroll
        for (int o = 16; o; o >>= 1) {
            float ov = __shfl_xor_sync(0xFFFFFFFFu, bv, o);
            int   oi = __shfl_xor_sync(0xFFFFFFFFu, bi, o);
            if (ov > bv || (ov == bv && oi < bi)) { bv = ov; bi = oi; }
        }
        if ((t & 31) == 0) { s_val[t >> 5] = bv; s_idx[t >> 5] = bi; }
        __syncthreads();
        if (t == 0) {
            for (int w = 1; w < 32; w++) {
                if (s_val[w] > bv || (s_val[w] == bv && s_idx[w] < bi)) {
                    bv = s_val[w]; bi = s_idx[w];
                }
            }
            selv[j] = bi;
            if (j == TOPK - 1) { s_thresh = bv - 5e-4f; ncand = 0; }
        }
        __syncthreads();
    }

    // Phase 2: collect candidates near/above the approx 5th value
    float thr = s_thresh;
    for (int v = t; v < VV; v += 1024) {
        if (row[v] >= thr) {
            int i = atomicAdd(&ncand, 1);
            if (i < NCAND) cand[i] = v;
        }
    }
    __syncthreads();
    int nc = min(ncand, NCAND);

    // Phase 3: exact fp32 recompute for candidates (one warp per candidate)
    {
        int wd = t >> 5, lane = t & 31;
        const float4* ts4 = reinterpret_cast<const float4*>(g_tse[b]);
        for (int ci = wd; ci < nc; ci += 32) {
            int v = cand[ci];
            const float4* lx4 = reinterpret_cast<const float4*>(lex + (size_t)v * DD);
            float d = 0.f;
            #pragma unroll
            for (int j = 0; j < 8; j++) {
                float4 a = ts4[j * 32 + lane];
                float4 c = lx4[j * 32 + lane];
                d += a.x * c.x + a.y * c.y + a.z * c.z + a.w * c.w;
            }
            #pragma unroll
            for (int o = 16; o; o >>= 1) d += __shfl_xor_sync(0xFFFFFFFFu, d, o);
            if (lane == 0)
                cval[ci] = d / fmaxf(g_xnorm[b] * g_ynorm[v], 1e-8f);
        }
    }
    __syncthreads();

    // Phase 4: exact top-5 over candidates (warp 0), tie-break lowest index
    if (t < 32) {
        for (int j = 0; j < TOPK; j++) {
            float bv = -1e30f;
            int bvi = 0x7FFFFFFF;
            int bci = -1;
            for (int ci = t; ci < nc; ci += 32) {
                bool used = false;
                #pragma unroll
                for (int jj = 0; jj < TOPK; jj++)
                    if (jj < j && selci[jj] == ci) used = true;
                if (used) continue;
                float x = cval[ci];
                int v = cand[ci];
                if (x > bv || (x == bv && v < bvi)) { bv = x; bvi = v; bci = ci; }
            }
            #pragma unroll
            for (int o = 16; o; o >>= 1) {
                float ov  = __shfl_xor_sync(0xFFFFFFFFu, bv, o);
                int   ovi = __shfl_xor_sync(0xFFFFFFFFu, bvi, o);
                int   oci = __shfl_xor_sync(0xFFFFFFFFu, bci, o);
                if (ov > bv || (ov == bv && ovi < bvi)) { bv = ov; bvi = ovi; bci = oci; }
            }
            if (t == 0) { selci[j] = bci; selfin[j] = bvi; }
            __syncwarp();
        }
    }
    __syncthreads();

    // Phase 5: gather top-k lexicon rows (exact order)
    for (int j = 0; j < TOPK; j++) {
        const float4* src = reinterpret_cast<const float4*>(lex + (size_t)selfin[j] * DD);
        float4* dst = reinterpret_cast<float4*>(out_topk + ((size_t)b * TOPK + j) * DD);
        for (int d = t; d < DD / 4; d += 1024) dst[d] = src[d];
    }
}

// ---------------------------------------------------------------------------
extern "C" void kernel_launch(void* const* d_in, const int* in_sizes, int n_in,
                              void* d_out, int out_size) {
    const float* patch = (const float*)d_in[0];
    const float* lex   = (const float*)d_in[1];
    float* out      = (float*)d_out;
    float* out_topk = out;                                  // [64][5][1024]
    float* out_sim  = out + (size_t)BB * TOPK * DD;         // [64][50257]

    mean_partial_kernel<<<dim3(NCHUNK, BB), 256>>>(patch);
    finalize_kernel<<<BB, 256>>>();
    gemm_kernel<<<(VV + TNB - 1) / TNB, 256>>>(lex, out_sim);
    topk_kernel<<<BB, 1024>>>(lex, out_sim, out_topk);
}

// round 4
// speedup vs baseline: 2.0157x; 1.2874x over previous
#include <cuda_runtime.h>
#include <cuda_bf16.h>
#include <math.h>
#include <cstdint>

// Problem dims (fixed for this bench)
#define BB 64
#define LL 2048
#define DD 1024
#define VV 50257
#define TOPK 5

#define NCHUNK 16
#define LPC (LL / NCHUNK)        // 128 rows per chunk

#define TNB 128                  // GEMM N tile
#define TK 32                    // GEMM K tile
#define KPAD 36                  // padded k stride (conflict-free for LDS.32 frags + STS.128)
#define NCAND 256

#define GEMM_SMEM ((2 * BB * KPAD + 2 * TNB * KPAD + BB + TNB) * 4)

// Scratch (device globals; no allocations allowed)
__device__ float4 g_part[NCHUNK][BB][DD / 4];  // mean-pool partials (4 MB)
__device__ float  g_tse[BB][DD];               // exact fp32 pooled embeddings
__device__ float  g_ts32[BB][DD];              // tf32-rounded pooled embeddings
__device__ float  g_xnorm[BB];
__device__ float  g_ynorm[VV];

__device__ __forceinline__ float tf32r(float x) {
    uint32_t o;
    asm("cvt.rna.tf32.f32 %0, %1;" : "=r"(o) : "f"(x));
    return __uint_as_float(o);
}

__device__ __forceinline__ void mma_tf32(float c[4],
                                         uint32_t a0, uint32_t a1, uint32_t a2, uint32_t a3,
                                         uint32_t b0, uint32_t b1) {
    asm volatile(
        "mma.sync.aligned.m16n8k8.row.col.f32.tf32.tf32.f32 "
        "{%0,%1,%2,%3}, {%4,%5,%6,%7}, {%8,%9}, {%0,%1,%2,%3};"
        : "+f"(c[0]), "+f"(c[1]), "+f"(c[2]), "+f"(c[3])
        : "r"(a0), "r"(a1), "r"(a2), "r"(a3), "r"(b0), "r"(b1));
}

// Orderable float <-> uint mapping (total order matching float compare)
__device__ __forceinline__ unsigned int ford(float f) {
    unsigned int u = __float_as_uint(f);
    return (u & 0x80000000u) ? ~u : (u | 0x80000000u);
}
__device__ __forceinline__ float funord(unsigned int r) {
    unsigned int u = (r & 0x80000000u) ? (r & 0x7FFFFFFFu) : ~r;
    return __uint_as_float(u);
}

// Insert x into sorted-descending 5-array (drop smallest)
__device__ __forceinline__ void ins5(unsigned long long c[5], unsigned long long x) {
    if (x <= c[4]) return;
    c[4] = x;
    #pragma unroll
    for (int i = 3; i >= 0; i--) {
        if (c[i + 1] > c[i]) {
            unsigned long long t = c[i]; c[i] = c[i + 1]; c[i + 1] = t;
        }
    }
}

// ---------------------------------------------------------------------------
// Kernel 1: mean-pool partial sums. grid=(NCHUNK, BB), block=256 (float4 each)
// ---------------------------------------------------------------------------
__global__ void __launch_bounds__(256) mean_partial_kernel(const float* __restrict__ patch) {
    int t = threadIdx.x;
    int c = blockIdx.x;
    int b = blockIdx.y;
    const float4* p = reinterpret_cast<const float4*>(
                          patch + ((size_t)b * LL + (size_t)c * LPC) * DD) + t;
    float4 s = make_float4(0.f, 0.f, 0.f, 0.f);
    #pragma unroll 8
    for (int l = 0; l < LPC; l++) {
        float4 v = p[(size_t)l * (DD / 4)];
        s.x += v.x; s.y += v.y; s.z += v.z; s.w += v.w;
    }
    g_part[c][b][t] = s;
}

// ---------------------------------------------------------------------------
// Kernel 2: finalize mean, write exact + tf32 ts (m-major), x norms.
// grid=BB, block=256
// ---------------------------------------------------------------------------
__global__ void __launch_bounds__(256) finalize_kernel() {
    int b = blockIdx.x;
    int t = threadIdx.x;
    float4 s = make_float4(0.f, 0.f, 0.f, 0.f);
    #pragma unroll
    for (int c = 0; c < NCHUNK; c++) {
        float4 v = g_part[c][b][t];
        s.x += v.x; s.y += v.y; s.z += v.z; s.w += v.w;
    }
    const float inv = 1.0f / (float)LL;
    s.x *= inv; s.y *= inv; s.z *= inv; s.w *= inv;
    reinterpret_cast<float4*>(g_tse[b])[t] = s;
    float4 r;
    r.x = tf32r(s.x); r.y = tf32r(s.y); r.z = tf32r(s.z); r.w = tf32r(s.w);
    reinterpret_cast<float4*>(g_ts32[b])[t] = r;

    float ss = s.x * s.x + s.y * s.y + s.z * s.z + s.w * s.w;
    #pragma unroll
    for (int o = 16; o; o >>= 1) ss += __shfl_xor_sync(0xFFFFFFFFu, ss, o);
    __shared__ float red[8];
    if ((t & 31) == 0) red[t >> 5] = ss;
    __syncthreads();
    if (t == 0) {
        float tot = 0.f;
        #pragma unroll
        for (int w = 0; w < 8; w++) tot += red[w];
        g_xnorm[b] = sqrtf(tot);
    }
}

// ---------------------------------------------------------------------------
// Kernel 3: TF32 tensor-core similarity GEMM + fused lexicon row norms.
// Double-buffered smem pipeline (one sync per k-iter, LDG prefetch overlaps
// compute). grid = ceil(VV/128), block = 256 (2 m-warps x 4 n-warps, 32x32
// warp tile via m16n8k8). Dynamic smem = GEMM_SMEM (56 KB).
// ---------------------------------------------------------------------------
__global__ void __launch_bounds__(256, 2) gemm_kernel(const float* __restrict__ lex,
                                                      float* __restrict__ out_sim) {
    extern __shared__ float smem[];
    float* As   = smem;                       // [2][BB*KPAD]
    float* Bs   = smem + 2 * BB * KPAD;       // [2][TNB*KPAD]
    float* s_xn = Bs + 2 * TNB * KPAD;        // [BB]
    float* s_yn = s_xn + BB;                  // [TNB]

    int tid = threadIdx.x;
    int v0 = blockIdx.x * TNB;
    int lane = tid & 31, wid = tid >> 5;
    int g = lane >> 2, t4 = lane & 3;
    int m_base = (wid >> 2) * 32;
    int n_base = (wid & 3) * 32;

    if (tid < BB) s_xn[tid] = g_xnorm[tid];

    // Per-thread tile-load coordinates
    const int am[2]  = { (tid) >> 3, (tid + 256) >> 3 };
    const int akq[2] = { ((tid) & 7) << 2, ((tid + 256) & 7) << 2 };
    int bn[4], bkq[4];
    #pragma unroll
    for (int i = 0; i < 4; i++) {
        int idx = tid + i * 256;
        bn[i] = idx >> 3;
        bkq[i] = (idx & 7) << 2;
    }

    float acc[2][4][4];
    #pragma unroll
    for (int mt = 0; mt < 2; mt++)
        #pragma unroll
        for (int nt = 0; nt < 4; nt++)
            #pragma unroll
            for (int r = 0; r < 4; r++) acc[mt][nt][r] = 0.f;
    float yacc[4] = {0.f, 0.f, 0.f, 0.f};

    float4 a_pre[2], b_pre[4];

    // ---- prologue: load tile 0, store to buffer 0 ----
    #pragma unroll
    for (int i = 0; i < 2; i++)
        a_pre[i] = *reinterpret_cast<const float4*>(&g_ts32[am[i]][akq[i]]);
    #pragma unroll
    for (int i = 0; i < 4; i++) {
        int v = v0 + bn[i];
        b_pre[i] = (v < VV)
            ? *reinterpret_cast<const float4*>(&lex[(size_t)v * DD + bkq[i]])
            : make_float4(0.f, 0.f, 0.f, 0.f);
    }
    {
        float* Ab = As; float* Bb = Bs;
        #pragma unroll
        for (int i = 0; i < 2; i++)
            *reinterpret_cast<float4*>(&Ab[am[i] * KPAD + akq[i]]) = a_pre[i];
        #pragma unroll
        for (int i = 0; i < 4; i++) {
            float4 w = b_pre[i];
            yacc[i] += w.x * w.x + w.y * w.y + w.z * w.z + w.w * w.w;
            float4 r;
            r.x = tf32r(w.x); r.y = tf32r(w.y); r.z = tf32r(w.z); r.w = tf32r(w.w);
            *reinterpret_cast<float4*>(&Bb[bn[i] * KPAD + bkq[i]]) = r;
        }
    }
    __syncthreads();

    const int NIT = DD / TK;  // 32
    for (int it = 0; it < NIT; it++) {
        int cur = it & 1;
        // ---- prefetch next tile (LDGs in flight during compute) ----
        if (it < NIT - 1) {
            int k0 = (it + 1) * TK;
            #pragma unroll
            for (int i = 0; i < 2; i++)
                a_pre[i] = *reinterpret_cast<const float4*>(&g_ts32[am[i]][k0 + akq[i]]);
            #pragma unroll
            for (int i = 0; i < 4; i++) {
                int v = v0 + bn[i];
                b_pre[i] = (v < VV)
                    ? *reinterpret_cast<const float4*>(&lex[(size_t)v * DD + k0 + bkq[i]])
                    : make_float4(0.f, 0.f, 0.f, 0.f);
            }
        }
        // ---- compute on current buffer ----
        {
            const float* Ab = As + cur * BB * KPAD;
            const float* Bb = Bs + cur * TNB * KPAD;
            #pragma unroll
            for (int ks = 0; ks < 4; ks++) {
                int kk = ks * 8 + t4;
                uint32_t a[2][4], bf[4][2];
                #pragma unroll
                for (int mt = 0; mt < 2; mt++) {
                    int r0 = m_base + 16 * mt + g;
                    a[mt][0] = __float_as_uint(Ab[r0 * KPAD + kk]);
                    a[mt][1] = __float_as_uint(Ab[(r0 + 8) * KPAD + kk]);
                    a[mt][2] = __float_as_uint(Ab[r0 * KPAD + kk + 4]);
                    a[mt][3] = __float_as_uint(Ab[(r0 + 8) * KPAD + kk + 4]);
                }
                #pragma unroll
                for (int nt = 0; nt < 4; nt++) {
                    int c0 = n_base + 8 * nt + g;
                    bf[nt][0] = __float_as_uint(Bb[c0 * KPAD + kk]);
                    bf[nt][1] = __float_as_uint(Bb[c0 * KPAD + kk + 4]);
                }
                #pragma unroll
                for (int mt = 0; mt < 2; mt++)
                    #pragma unroll
                    for (int nt = 0; nt < 4; nt++)
                        mma_tf32(acc[mt][nt], a[mt][0], a[mt][1], a[mt][2], a[mt][3],
                                 bf[nt][0], bf[nt][1]);
            }
        }
        // ---- store prefetched tile into other buffer ----
        if (it < NIT - 1) {
            float* Ab = As + (1 - cur) * BB * KPAD;
            float* Bb = Bs + (1 - cur) * TNB * KPAD;
            #pragma unroll
            for (int i = 0; i < 2; i++)
                *reinterpret_cast<float4*>(&Ab[am[i] * KPAD + akq[i]]) = a_pre[i];
            #pragma unroll
            for (int i = 0; i < 4; i++) {
                float4 w = b_pre[i];
                yacc[i] += w.x * w.x + w.y * w.y + w.z * w.z + w.w * w.w;
                float4 r;
                r.x = tf32r(w.x); r.y = tf32r(w.y); r.z = tf32r(w.z); r.w = tf32r(w.w);
                *reinterpret_cast<float4*>(&Bb[bn[i] * KPAD + bkq[i]]) = r;
            }
            __syncthreads();
        }
    }

    // Fused y norms: reduce the 8 k-slice partials per row (groups of 8 lanes)
    #pragma unroll
    for (int i = 0; i < 4; i++) {
        float ys = yacc[i];
        ys += __shfl_down_sync(0xFFFFFFFFu, ys, 4, 8);
        ys += __shfl_down_sync(0xFFFFFFFFu, ys, 2, 8);
        ys += __shfl_down_sync(0xFFFFFFFFu, ys, 1, 8);
        if ((tid & 7) == 0) {
            int n = (tid + i * 256) >> 3;
            float yn = sqrtf(ys);
            s_yn[n] = yn;
            if (v0 + n < VV) g_ynorm[v0 + n] = yn;
        }
    }
    __syncthreads();

    // Epilogue: normalize, store. c0:(g,2t4) c1:(g,2t4+1) c2:(g+8,2t4) c3:(g+8,2t4+1)
    #pragma unroll
    for (int mt = 0; mt < 2; mt++) {
        int m0 = m_base + 16 * mt + g;
        float xn0 = s_xn[m0], xn1 = s_xn[m0 + 8];
        #pragma unroll
        for (int nt = 0; nt < 4; nt++) {
            int ncol = n_base + 8 * nt + 2 * t4;
            #pragma unroll
            for (int j = 0; j < 2; j++) {
                int v = v0 + ncol + j;
                if (v < VV) {
                    float yn = s_yn[ncol + j];
                    out_sim[(size_t)m0 * VV + v] =
                        acc[mt][nt][j] / fmaxf(xn0 * yn, 1e-8f);
                    out_sim[(size_t)(m0 + 8) * VV + v] =
                        acc[mt][nt][2 + j] / fmaxf(xn1 * yn, 1e-8f);
                }
            }
        }
    }
}

// ---------------------------------------------------------------------------
// Kernel 4: exact top-k. Single-pass register top-5 over packed keys ->
// candidate set within 5e-4 of the 5th value -> exact fp32 recompute ->
// exact (val desc, idx asc) selection -> gather. grid=BB, block=1024.
// ---------------------------------------------------------------------------
__global__ void __launch_bounds__(1024) topk_kernel(const float* __restrict__ lex,
                                                    const float* __restrict__ sim,
                                                    float* __restrict__ out_topk) {
    int b = blockIdx.x;
    int t = threadIdx.x;
    int lane = t & 31, wid = t >> 5;

    __shared__ unsigned long long wtop[32][5];
    __shared__ float s_thresh;
    __shared__ int   cand[NCAND];
    __shared__ float cval[NCAND];
    __shared__ int   ncand;
    __shared__ int   selci[TOPK];
    __shared__ int   selfin[TOPK];

    const float* row = sim + (size_t)b * VV;

    // Phase 1: single-pass approximate top-5.
    // key = (orderable(value) << 32) | (VV-1-v): larger key = larger value,
    // tie -> lower index. Keys are unique (index field).
    unsigned long long t5[5] = {0ull, 0ull, 0ull, 0ull, 0ull};
    for (int v = t; v < VV; v += 1024) {
        unsigned long long k =
            ((unsigned long long)ford(row[v]) << 32) | (unsigned)(VV - 1 - v);
        ins5(t5, k);
    }
    // warp butterfly merge
    #pragma unroll
    for (int o = 16; o; o >>= 1) {
        unsigned long long ot[5];
        #pragma unroll
        for (int i = 0; i < 5; i++) ot[i] = __shfl_xor_sync(0xFFFFFFFFu, t5[i], o);
        #pragma unroll
        for (int i = 0; i < 5; i++) ins5(t5, ot[i]);
    }
    if (lane == 0) {
        #pragma unroll
        for (int i = 0; i < 5; i++) wtop[wid][i] = t5[i];
    }
    __syncthreads();
    if (wid == 0) {
        unsigned long long m5[5];
        #pragma unroll
        for (int i = 0; i < 5; i++) m5[i] = wtop[lane][i];
        #pragma unroll
        for (int o = 16; o; o >>= 1) {
            unsigned long long ot[5];
            #pragma unroll
            for (int i = 0; i < 5; i++) ot[i] = __shfl_xor_sync(0xFFFFFFFFu, m5[i], o);
            #pragma unroll
            for (int i = 0; i < 5; i++) ins5(m5, ot[i]);
        }
        if (lane == 0) {
            float f5 = funord((unsigned)(m5[4] >> 32));
            s_thresh = f5 - 5e-4f;
            ncand = 0;
        }
    }
    __syncthreads();

    // Phase 2: collect candidates near/above the approx 5th value
    float thr = s_thresh;
    for (int v = t; v < VV; v += 1024) {
        if (row[v] >= thr) {
            int i = atomicAdd(&ncand, 1);
            if (i < NCAND) cand[i] = v;
        }
    }
    __syncthreads();
    int nc = min(ncand, NCAND);

    // Phase 3: exact fp32 recompute for candidates (one warp per candidate)
    {
        const float4* ts4 = reinterpret_cast<const float4*>(g_tse[b]);
        for (int ci = wid; ci < nc; ci += 32) {
            int v = cand[ci];
            const float4* lx4 = reinterpret_cast<const float4*>(lex + (size_t)v * DD);
            float d = 0.f;
            #pragma unroll
            for (int j = 0; j < 8; j++) {
                float4 a = ts4[j * 32 + lane];
                float4 c = lx4[j * 32 + lane];
                d += a.x * c.x + a.y * c.y + a.z * c.z + a.w * c.w;
            }
            #pragma unroll
            for (int o = 16; o; o >>= 1) d += __shfl_xor_sync(0xFFFFFFFFu, d, o);
            if (lane == 0)
                cval[ci] = d / fmaxf(g_xnorm[b] * g_ynorm[v], 1e-8f);
        }
    }
    __syncthreads();

    // Phase 4: exact top-5 over candidates (warp 0), tie-break lowest index
    if (t < 32) {
        for (int j = 0; j < TOPK; j++) {
            float bv = -1e30f;
            int bvi = 0x7FFFFFFF;
            int bci = -1;
            for (int ci = t; ci < nc; ci += 32) {
                bool used = false;
                #pragma unroll
                for (int jj = 0; jj < TOPK; jj++)
                    if (jj < j && selci[jj] == ci) used = true;
                if (used) continue;
                float x = cval[ci];
                int v = cand[ci];
                if (x > bv || (x == bv && v < bvi)) { bv = x; bvi = v; bci = ci; }
            }
            #pragma unroll
            for (int o = 16; o; o >>= 1) {
                float ov  = __shfl_xor_sync(0xFFFFFFFFu, bv, o);
                int   ovi = __shfl_xor_sync(0xFFFFFFFFu, bvi, o);
                int   oci = __shfl_xor_sync(0xFFFFFFFFu, bci, o);
                if (ov > bv || (ov == bv && ovi < bvi)) { bv = ov; bvi = ovi; bci = oci; }
            }
            if (t == 0) { selci[j] = bci; selfin[j] = bvi; }
            __syncwarp();
        }
    }
    __syncthreads();

    // Phase 5: gather top-k lexicon rows (exact order)
    for (int j = 0; j < TOPK; j++) {
        const float4* src = reinterpret_cast<const float4*>(lex + (size_t)selfin[j] * DD);
        float4* dst = reinterpret_cast<float4*>(out_topk + ((size_t)b * TOPK + j) * DD);
        for (int d = t; d < DD / 4; d += 1024) dst[d] = src[d];
    }
}

// ---------------------------------------------------------------------------
extern "C" void kernel_launch(void* const* d_in, const int* in_sizes, int n_in,
                              void* d_out, int out_size) {
    const float* patch = (const float*)d_in[0];
    const float* lex   = (const float*)d_in[1];
    float* out      = (float*)d_out;
    float* out_topk = out;                                  // [64][5][1024]
    float* out_sim  = out + (size_t)BB * TOPK * DD;         // [64][50257]

    cudaFuncSetAttribute(gemm_kernel, cudaFuncAttributeMaxDynamicSharedMemorySize,
                         GEMM_SMEM);

    mean_partial_kernel<<<dim3(NCHUNK, BB), 256>>>(patch);
    finalize_kernel<<<BB, 256>>>();
    gemm_kernel<<<(VV + TNB - 1) / TNB, 256, GEMM_SMEM>>>(lex, out_sim);
    topk_kernel<<<BB, 1024>>>(lex, out_sim, out_topk);
}

// round 5
// speedup vs baseline: 2.0622x; 1.0230x over previous
#include <cuda_runtime.h>
#include <cuda_bf16.h>
#include <math.h>
#include <cstdint>

// Problem dims (fixed for this bench)
#define BB 64
#define LL 2048
#define DD 1024
#define VV 50257
#define TOPK 5

#define NCHUNK 16
#define LPC (LL / NCHUNK)        // 128 rows per chunk

#define TNB 128                  // GEMM N tile
#define NBLK ((VV + TNB - 1) / TNB)   // 393
#define TK 32                    // GEMM K tile
#define KPAD 36                  // padded k stride (conflict-free frag LDS + STS.128)
#define NCAND 64
#define BTOP 6                   // per-block-per-row top-K kept
#define CSPAD 129                // Cs row stride

#define GEMM_SMEM ((2 * BB * KPAD + 2 * TNB * KPAD + BB + TNB) * 4)

typedef unsigned long long u64;

// Scratch (device globals; no allocations allowed)
__device__ float4 g_part[NCHUNK][BB][DD / 4];  // mean-pool partials (4 MB)
__device__ float  g_tse[BB][DD];               // exact fp32 pooled embeddings
__device__ float  g_ts32[BB][DD];              // tf32-rounded pooled embeddings
__device__ float  g_xnorm[BB];
__device__ float  g_ynorm[VV];
__device__ u64    g_btop[BB][NBLK][BTOP];      // per-(row,block) top-6 keys (1.2 MB)

__device__ __forceinline__ float tf32r(float x) {
    uint32_t o;
    asm("cvt.rna.tf32.f32 %0, %1;" : "=r"(o) : "f"(x));
    return __uint_as_float(o);
}

__device__ __forceinline__ void mma_tf32(float c[4],
                                         uint32_t a0, uint32_t a1, uint32_t a2, uint32_t a3,
                                         uint32_t b0, uint32_t b1) {
    asm volatile(
        "mma.sync.aligned.m16n8k8.row.col.f32.tf32.tf32.f32 "
        "{%0,%1,%2,%3}, {%4,%5,%6,%7}, {%8,%9}, {%0,%1,%2,%3};"
        : "+f"(c[0]), "+f"(c[1]), "+f"(c[2]), "+f"(c[3])
        : "r"(a0), "r"(a1), "r"(a2), "r"(a3), "r"(b0), "r"(b1));
}

// Orderable float <-> uint mapping (total order matching float compare)
__device__ __forceinline__ unsigned int ford(float f) {
    unsigned int u = __float_as_uint(f);
    return (u & 0x80000000u) ? ~u : (u | 0x80000000u);
}
__device__ __forceinline__ float funord(unsigned int r) {
    unsigned int u = (r & 0x80000000u) ? (r & 0x7FFFFFFFu) : ~r;
    return __uint_as_float(u);
}

// key = (orderable(value) << 32) | (VV-1-v): bigger = better, tie -> lower idx
__device__ __forceinline__ u64 mkkey(float val, int v) {
    return ((u64)ford(val) << 32) | (unsigned)(VV - 1 - v);
}
__device__ __forceinline__ int key2idx(u64 k) {
    return VV - 1 - (int)(unsigned)(k & 0xFFFFFFFFu);
}

// Insert x into sorted-descending K-array (drop smallest)
template <int K>
__device__ __forceinline__ void insK(u64 c[K], u64 x) {
    if (x <= c[K - 1]) return;
    c[K - 1] = x;
    #pragma unroll
    for (int i = K - 2; i >= 0; i--) {
        if (c[i + 1] > c[i]) {
            u64 t = c[i]; c[i] = c[i + 1]; c[i + 1] = t;
        }
    }
}

// ---------------------------------------------------------------------------
// Kernel 1: mean-pool partial sums. grid=(NCHUNK, BB), block=256 (float4 each)
// ---------------------------------------------------------------------------
__global__ void __launch_bounds__(256) mean_partial_kernel(const float* __restrict__ patch) {
    int t = threadIdx.x;
    int c = blockIdx.x;
    int b = blockIdx.y;
    const float4* p = reinterpret_cast<const float4*>(
                          patch + ((size_t)b * LL + (size_t)c * LPC) * DD) + t;
    float4 s = make_float4(0.f, 0.f, 0.f, 0.f);
    #pragma unroll 8
    for (int l = 0; l < LPC; l++) {
        float4 v = p[(size_t)l * (DD / 4)];
        s.x += v.x; s.y += v.y; s.z += v.z; s.w += v.w;
    }
    g_part[c][b][t] = s;
}

// ---------------------------------------------------------------------------
// Kernel 2: finalize mean, write exact + tf32 ts, x norms. grid=BB, block=256
// ---------------------------------------------------------------------------
__global__ void __launch_bounds__(256) finalize_kernel() {
    int b = blockIdx.x;
    int t = threadIdx.x;
    float4 s = make_float4(0.f, 0.f, 0.f, 0.f);
    #pragma unroll
    for (int c = 0; c < NCHUNK; c++) {
        float4 v = g_part[c][b][t];
        s.x += v.x; s.y += v.y; s.z += v.z; s.w += v.w;
    }
    const float inv = 1.0f / (float)LL;
    s.x *= inv; s.y *= inv; s.z *= inv; s.w *= inv;
    reinterpret_cast<float4*>(g_tse[b])[t] = s;
    float4 r;
    r.x = tf32r(s.x); r.y = tf32r(s.y); r.z = tf32r(s.z); r.w = tf32r(s.w);
    reinterpret_cast<float4*>(g_ts32[b])[t] = r;

    float ss = s.x * s.x + s.y * s.y + s.z * s.z + s.w * s.w;
    #pragma unroll
    for (int o = 16; o; o >>= 1) ss += __shfl_xor_sync(0xFFFFFFFFu, ss, o);
    __shared__ float red[8];
    if ((t & 31) == 0) red[t >> 5] = ss;
    __syncthreads();
    if (t == 0) {
        float tot = 0.f;
        #pragma unroll
        for (int w = 0; w < 8; w++) tot += red[w];
        g_xnorm[b] = sqrtf(tot);
    }
}

// ---------------------------------------------------------------------------
// Kernel 3: TF32 tensor-core similarity GEMM + fused y-norms + fused per-block
// top-6. Double-buffered smem pipeline. grid=NBLK, block=256.
// ---------------------------------------------------------------------------
__global__ void __launch_bounds__(256, 2) gemm_kernel(const float* __restrict__ lex,
                                                      float* __restrict__ out_sim) {
    extern __shared__ float smem[];
    float* As   = smem;                       // [2][BB*KPAD]
    float* Bs   = smem + 2 * BB * KPAD;       // [2][TNB*KPAD]
    float* s_xn = Bs + 2 * TNB * KPAD;        // [BB]
    float* s_yn = s_xn + BB;                  // [TNB]
    // Epilogue overlay (after mainloop, on top of As/Bs):
    float* Cs   = smem;                       // [BB][CSPAD]  33.0 KB
    u64*   tmp  = reinterpret_cast<u64*>(smem + BB * CSPAD + (BB * CSPAD & 1));
                                              // [256][BTOP] 12.3 KB (8B aligned)

    int tid = threadIdx.x;
    int v0 = blockIdx.x * TNB;
    int lane = tid & 31, wid = tid >> 5;
    int g = lane >> 2, t4 = lane & 3;
    int m_base = (wid >> 2) * 32;
    int n_base = (wid & 3) * 32;

    if (tid < BB) s_xn[tid] = g_xnorm[tid];

    const int am[2]  = { (tid) >> 3, (tid + 256) >> 3 };
    const int akq[2] = { ((tid) & 7) << 2, ((tid + 256) & 7) << 2 };
    int bn[4], bkq[4];
    #pragma unroll
    for (int i = 0; i < 4; i++) {
        int idx = tid + i * 256;
        bn[i] = idx >> 3;
        bkq[i] = (idx & 7) << 2;
    }

    float acc[2][4][4];
    #pragma unroll
    for (int mt = 0; mt < 2; mt++)
        #pragma unroll
        for (int nt = 0; nt < 4; nt++)
            #pragma unroll
            for (int r = 0; r < 4; r++) acc[mt][nt][r] = 0.f;
    float yacc[4] = {0.f, 0.f, 0.f, 0.f};

    float4 a_pre[2], b_pre[4];

    // ---- prologue: load tile 0 into buffer 0 ----
    #pragma unroll
    for (int i = 0; i < 2; i++)
        a_pre[i] = *reinterpret_cast<const float4*>(&g_ts32[am[i]][akq[i]]);
    #pragma unroll
    for (int i = 0; i < 4; i++) {
        int v = v0 + bn[i];
        b_pre[i] = (v < VV)
            ? *reinterpret_cast<const float4*>(&lex[(size_t)v * DD + bkq[i]])
            : make_float4(0.f, 0.f, 0.f, 0.f);
    }
    #pragma unroll
    for (int i = 0; i < 2; i++)
        *reinterpret_cast<float4*>(&As[am[i] * KPAD + akq[i]]) = a_pre[i];
    #pragma unroll
    for (int i = 0; i < 4; i++) {
        float4 w = b_pre[i];
        yacc[i] += w.x * w.x + w.y * w.y + w.z * w.z + w.w * w.w;
        float4 r;
        r.x = tf32r(w.x); r.y = tf32r(w.y); r.z = tf32r(w.z); r.w = tf32r(w.w);
        *reinterpret_cast<float4*>(&Bs[bn[i] * KPAD + bkq[i]]) = r;
    }
    __syncthreads();

    const int NIT = DD / TK;  // 32
    for (int it = 0; it < NIT; it++) {
        int cur = it & 1;
        if (it < NIT - 1) {
            int k0 = (it + 1) * TK;
            #pragma unroll
            for (int i = 0; i < 2; i++)
                a_pre[i] = *reinterpret_cast<const float4*>(&g_ts32[am[i]][k0 + akq[i]]);
            #pragma unroll
            for (int i = 0; i < 4; i++) {
                int v = v0 + bn[i];
                b_pre[i] = (v < VV)
                    ? *reinterpret_cast<const float4*>(&lex[(size_t)v * DD + k0 + bkq[i]])
                    : make_float4(0.f, 0.f, 0.f, 0.f);
            }
        }
        {
            const float* Ab = As + cur * BB * KPAD;
            const float* Bb = Bs + cur * TNB * KPAD;
            #pragma unroll
            for (int ks = 0; ks < 4; ks++) {
                int kk = ks * 8 + t4;
                uint32_t a[2][4], bf[4][2];
                #pragma unroll
                for (int mt = 0; mt < 2; mt++) {
                    int r0 = m_base + 16 * mt + g;
                    a[mt][0] = __float_as_uint(Ab[r0 * KPAD + kk]);
                    a[mt][1] = __float_as_uint(Ab[(r0 + 8) * KPAD + kk]);
                    a[mt][2] = __float_as_uint(Ab[r0 * KPAD + kk + 4]);
                    a[mt][3] = __float_as_uint(Ab[(r0 + 8) * KPAD + kk + 4]);
                }
                #pragma unroll
                for (int nt = 0; nt < 4; nt++) {
                    int c0 = n_base + 8 * nt + g;
                    bf[nt][0] = __float_as_uint(Bb[c0 * KPAD + kk]);
                    bf[nt][1] = __float_as_uint(Bb[c0 * KPAD + kk + 4]);
                }
                #pragma unroll
                for (int mt = 0; mt < 2; mt++)
                    #pragma unroll
                    for (int nt = 0; nt < 4; nt++)
                        mma_tf32(acc[mt][nt], a[mt][0], a[mt][1], a[mt][2], a[mt][3],
                                 bf[nt][0], bf[nt][1]);
            }
        }
        if (it < NIT - 1) {
            float* Ab = As + (1 - cur) * BB * KPAD;
            float* Bb = Bs + (1 - cur) * TNB * KPAD;
            #pragma unroll
            for (int i = 0; i < 2; i++)
                *reinterpret_cast<float4*>(&Ab[am[i] * KPAD + akq[i]]) = a_pre[i];
            #pragma unroll
            for (int i = 0; i < 4; i++) {
                float4 w = b_pre[i];
                yacc[i] += w.x * w.x + w.y * w.y + w.z * w.z + w.w * w.w;
                float4 r;
                r.x = tf32r(w.x); r.y = tf32r(w.y); r.z = tf32r(w.z); r.w = tf32r(w.w);
                *reinterpret_cast<float4*>(&Bb[bn[i] * KPAD + bkq[i]]) = r;
            }
            __syncthreads();
        }
    }

    // ---- y norms (before smem overlay: s_yn lives past the overlay region) ----
    #pragma unroll
    for (int i = 0; i < 4; i++) {
        float ys = yacc[i];
        ys += __shfl_down_sync(0xFFFFFFFFu, ys, 4, 8);
        ys += __shfl_down_sync(0xFFFFFFFFu, ys, 2, 8);
        ys += __shfl_down_sync(0xFFFFFFFFu, ys, 1, 8);
        if ((tid & 7) == 0) {
            int n = (tid + i * 256) >> 3;
            float yn = sqrtf(ys);
            s_yn[n] = yn;
            if (v0 + n < VV) g_ynorm[v0 + n] = yn;
        }
    }
    __syncthreads();  // all warps done with As/Bs + s_yn ready

    // ---- stage normalized tile in smem (Cs overlays As/Bs) ----
    #pragma unroll
    for (int mt = 0; mt < 2; mt++) {
        int m0 = m_base + 16 * mt + g;
        float xn0 = s_xn[m0], xn1 = s_xn[m0 + 8];
        #pragma unroll
        for (int nt = 0; nt < 4; nt++) {
            int ncol = n_base + 8 * nt + 2 * t4;
            #pragma unroll
            for (int j = 0; j < 2; j++) {
                int v = v0 + ncol + j;
                float yn = s_yn[ncol + j];
                float s0 = acc[mt][nt][j]     / fmaxf(xn0 * yn, 1e-8f);
                float s1 = acc[mt][nt][2 + j] / fmaxf(xn1 * yn, 1e-8f);
                if (v >= VV) { s0 = -3.4e38f; s1 = -3.4e38f; }
                Cs[m0 * CSPAD + ncol + j]       = s0;
                Cs[(m0 + 8) * CSPAD + ncol + j] = s1;
            }
        }
    }
    __syncthreads();

    // ---- coalesced out_sim write ----
    #pragma unroll
    for (int i = 0; i < 32; i++) {
        int idx = tid + i * 256;
        int m = idx >> 7, col = idx & 127;
        int v = v0 + col;
        if (v < VV)
            out_sim[(size_t)m * VV + v] = Cs[m * CSPAD + col];
    }

    // ---- per-row top-6: 4 threads/row, 32 cols each ----
    {
        int row = tid >> 2, q = tid & 3;
        u64 t6[BTOP] = {0, 0, 0, 0, 0, 0};
        #pragma unroll
        for (int i = 0; i < 32; i++) {
            int col = q * 32 + i;
            int v = v0 + col;
            if (v < VV) insK<BTOP>(t6, mkkey(Cs[row * CSPAD + col], v));
        }
        #pragma unroll
        for (int i = 0; i < BTOP; i++) tmp[tid * BTOP + i] = t6[i];
    }
    __syncthreads();
    if (tid < BB) {
        u64 t6[BTOP] = {0, 0, 0, 0, 0, 0};
        #pragma unroll
        for (int q = 0; q < 4; q++)
            #pragma unroll
            for (int i = 0; i < BTOP; i++)
                insK<BTOP>(t6, tmp[(tid * 4 + q) * BTOP + i]);
        #pragma unroll
        for (int i = 0; i < BTOP; i++) g_btop[tid][blockIdx.x][i] = t6[i];
    }
}

// ---------------------------------------------------------------------------
// Kernel 4: merge per-block top-6 keys -> approx top-5 -> threshold candidates
// -> exact fp32 recompute -> exact select -> gather. grid=BB, block=256.
// ---------------------------------------------------------------------------
__global__ void __launch_bounds__(256) merge_kernel(const float* __restrict__ lex,
                                                    float* __restrict__ out_topk) {
    int b = blockIdx.x;
    int t = threadIdx.x;
    int lane = t & 31, wid = t >> 5;

    __shared__ u64   wtop[8][5];
    __shared__ float s_thresh;
    __shared__ int   cand[NCAND];
    __shared__ float cval[NCAND];
    __shared__ int   ncand;
    __shared__ int   selci[TOPK];
    __shared__ int   selfin[TOPK];

    const u64* keys = &g_btop[b][0][0];
    const int NK = NBLK * BTOP;  // 2358

    // Phase A: block-wide top-5 over keys
    u64 t5[5] = {0, 0, 0, 0, 0};
    for (int i = t; i < NK; i += 256) insK<5>(t5, keys[i]);
    #pragma unroll
    for (int o = 16; o; o >>= 1) {
        u64 ot[5];
        #pragma unroll
        for (int i = 0; i < 5; i++) ot[i] = __shfl_xor_sync(0xFFFFFFFFu, t5[i], o);
        #pragma unroll
        for (int i = 0; i < 5; i++) insK<5>(t5, ot[i]);
    }
    if (lane == 0) {
        #pragma unroll
        for (int i = 0; i < 5; i++) wtop[wid][i] = t5[i];
    }
    __syncthreads();
    if (wid == 0) {
        const u64* flat = &wtop[0][0];  // 40 keys
        u64 m5[5] = {0, 0, 0, 0, 0};
        insK<5>(m5, flat[lane]);
        if (lane < 8) insK<5>(m5, flat[lane + 32]);
        #pragma unroll
        for (int o = 16; o; o >>= 1) {
            u64 ot[5];
            #pragma unroll
            for (int i = 0; i < 5; i++) ot[i] = __shfl_xor_sync(0xFFFFFFFFu, m5[i], o);
            #pragma unroll
            for (int i = 0; i < 5; i++) insK<5>(m5, ot[i]);
        }
        if (lane == 0) {
            s_thresh = funord((unsigned)(m5[4] >> 32)) - 5e-4f;
            ncand = 0;
        }
    }
    __syncthreads();

    // Phase B: candidates = keys with value >= thresh (unique by construction)
    float thr = s_thresh;
    for (int i = t; i < NK; i += 256) {
        u64 k = keys[i];
        if (funord((unsigned)(k >> 32)) >= thr) {
            int slot = atomicAdd(&ncand, 1);
            if (slot < NCAND) cand[slot] = key2idx(k);
        }
    }
    __syncthreads();
    int nc = min(ncand, NCAND);

    // Phase C: exact fp32 recompute (one warp per candidate)
    {
        const float4* ts4 = reinterpret_cast<const float4*>(g_tse[b]);
        for (int ci = wid; ci < nc; ci += 8) {
            int v = cand[ci];
            const float4* lx4 = reinterpret_cast<const float4*>(lex + (size_t)v * DD);
            float d = 0.f;
            #pragma unroll
            for (int j = 0; j < 8; j++) {
                float4 a = ts4[j * 32 + lane];
                float4 c = lx4[j * 32 + lane];
                d += a.x * c.x + a.y * c.y + a.z * c.z + a.w * c.w;
            }
            #pragma unroll
            for (int o = 16; o; o >>= 1) d += __shfl_xor_sync(0xFFFFFFFFu, d, o);
            if (lane == 0)
                cval[ci] = d / fmaxf(g_xnorm[b] * g_ynorm[v], 1e-8f);
        }
    }
    __syncthreads();

    // Phase D: exact top-5 over candidates (warp 0), tie-break lowest index
    if (t < 32) {
        for (int j = 0; j < TOPK; j++) {
            float bv = -1e30f;
            int bvi = 0x7FFFFFFF;
            int bci = -1;
            for (int ci = t; ci < nc; ci += 32) {
                bool used = false;
                #pragma unroll
                for (int jj = 0; jj < TOPK; jj++)
                    if (jj < j && selci[jj] == ci) used = true;
                if (used) continue;
                float x = cval[ci];
                int v = cand[ci];
                if (x > bv || (x == bv && v < bvi)) { bv = x; bvi = v; bci = ci; }
            }
            #pragma unroll
            for (int o = 16; o; o >>= 1) {
                float ov  = __shfl_xor_sync(0xFFFFFFFFu, bv, o);
                int   ovi = __shfl_xor_sync(0xFFFFFFFFu, bvi, o);
                int   oci = __shfl_xor_sync(0xFFFFFFFFu, bci, o);
                if (ov > bv || (ov == bv && ovi < bvi)) { bv = ov; bvi = ovi; bci = oci; }
            }
            if (t == 0) { selci[j] = bci; selfin[j] = bvi; }
            __syncwarp();
        }
    }
    __syncthreads();

    // Phase E: gather top-k lexicon rows
    for (int j = 0; j < TOPK; j++) {
        const float4* src = reinterpret_cast<const float4*>(lex + (size_t)selfin[j] * DD);
        float4* dst = reinterpret_cast<float4*>(out_topk + ((size_t)b * TOPK + j) * DD);
        if (t < DD / 4) dst[t] = src[t];
    }
}

// ---------------------------------------------------------------------------
extern "C" void kernel_launch(void* const* d_in, const int* in_sizes, int n_in,
                              void* d_out, int out_size) {
    const float* patch = (const float*)d_in[0];
    const float* lex   = (const float*)d_in[1];
    float* out      = (float*)d_out;
    float* out_topk = out;                                  // [64][5][1024]
    float* out_sim  = out + (size_t)BB * TOPK * DD;         // [64][50257]

    cudaFuncSetAttribute(gemm_kernel, cudaFuncAttributeMaxDynamicSharedMemorySize,
                         GEMM_SMEM);

    mean_partial_kernel<<<dim3(NCHUNK, BB), 256>>>(patch);
    finalize_kernel<<<BB, 256>>>();
    gemm_kernel<<<NBLK, 256, GEMM_SMEM>>>(lex, out_sim);
    merge_kernel<<<BB, 256>>>(lex, out_topk);
}